// round 14
// baseline (speedup 1.0000x reference)
#include <cuda_runtime.h>
#include <cuda_fp16.h>

#define B_DIM 1024
#define T_DIM 256
#define D_DIM 64
#define H_DIM 128
#define GH 256          // 2H
#define XCOLS 384       // 256 gate cols + 128 cand cols
#define RROWS 8
#define NGROUPS (B_DIM / RROWS)   // 128
#define XPAD 68         // proj x smem stride
#define WPAD 392        // proj W smem stride
#define HP 132          // gru fp32 h row stride (floats)
#define HP2 68          // gru half2 row stride (uint32 units)

// Scratch (device globals: no allocation allowed).
static __device__ float g_Xbuf[(size_t)B_DIM * T_DIM * XCOLS]; // ~402 MB
static __device__ int   g_perm[B_DIM];
static __device__ int   g_counter;   // kept for sort determinism (unused by gru)

__device__ __forceinline__ float tanh_fast(float z) {
    float r;
    asm("tanh.approx.f32 %0, %1;" : "=f"(r) : "f"(z));
    return r;
}
__device__ __forceinline__ float sigmoid_fast(float z) {
    return fmaf(0.5f, tanh_fast(0.5f * z), 0.5f);
}
__device__ __forceinline__ unsigned f2tf32(float f) {
    unsigned u;
    asm("cvt.rna.tf32.f32 %0, %1;" : "=r"(u) : "f"(f));
    return u;
}
__device__ __forceinline__ unsigned pack_h2(float lo, float hi) {
    __half2 h = __floats2half2_rn(lo, hi);
    return *(unsigned*)&h;
}
__device__ __forceinline__ void mma_tf32(float& c0, float& c1, float& c2, float& c3,
                                         unsigned a0, unsigned a1, unsigned a2, unsigned a3,
                                         unsigned b0, unsigned b1) {
    asm("mma.sync.aligned.m16n8k8.row.col.f32.tf32.tf32.f32 "
        "{%0,%1,%2,%3}, {%4,%5,%6,%7}, {%8,%9}, {%0,%1,%2,%3};"
        : "+f"(c0), "+f"(c1), "+f"(c2), "+f"(c3)
        : "r"(a0), "r"(a1), "r"(a2), "r"(a3), "r"(b0), "r"(b1));
}
__device__ __forceinline__ void mma_f16(float& c0, float& c1, float& c2, float& c3,
                                        unsigned a0, unsigned a1, unsigned a2, unsigned a3,
                                        unsigned b0, unsigned b1) {
    asm("mma.sync.aligned.m16n8k16.row.col.f32.f16.f16.f32 "
        "{%0,%1,%2,%3}, {%4,%5,%6,%7}, {%8,%9}, {%0,%1,%2,%3};"
        : "+f"(c0), "+f"(c1), "+f"(c2), "+f"(c3)
        : "r"(a0), "r"(a1), "r"(a2), "r"(a3), "r"(b0), "r"(b1));
}

// ---------------------------------------------------------------------------
// K0: counting sort rows by seq_len (descending, LPT) + reset counter.
// ---------------------------------------------------------------------------
__global__ void sort_kernel(const int* __restrict__ seq_lens) {
    __shared__ int hist[256];
    __shared__ int offs[256];
    int tid = threadIdx.x;
    hist[tid] = 0;
    __syncthreads();
    for (int r = tid; r < B_DIM; r += 256) {
        int L = seq_lens[r];
        L = min(max(L, 0), 255);
        atomicAdd(&hist[L], 1);
    }
    __syncthreads();
    if (tid == 0) {
        int run = 0;
        for (int k = 255; k >= 0; k--) { offs[k] = run; run += hist[k]; }
        g_counter = 0;
    }
    __syncthreads();
    for (int r = tid; r < B_DIM; r += 256) {
        int L = seq_lens[r];
        L = min(max(L, 0), 255);
        int pos = atomicAdd(&offs[L], 1);
        g_perm[pos] = r;
    }
}

// ---------------------------------------------------------------------------
// K1: projection via tf32 tensor cores + smem-staged coalesced epilogue.
// (unchanged — validated)
// ---------------------------------------------------------------------------
__global__ void __launch_bounds__(512) proj_kernel(
    const int* __restrict__ item_his,
    const int* __restrict__ seq_lens,
    const float* __restrict__ embedding,
    const float* __restrict__ gate_kernel,
    const float* __restrict__ gate_bias,
    const float* __restrict__ cand_kernel,
    const float* __restrict__ cand_bias)
{
    extern __shared__ unsigned smu[];
    unsigned* xs = smu;                      // [64][XPAD]
    unsigned* Wt = xs + 64 * XPAD;           // [64][WPAD] (reused as stage)
    float*    bs = (float*)(Wt + 64 * WPAD); // [384]
    __shared__ int items_s[64];

    int b  = blockIdx.y;
    int t0 = blockIdx.x * 64;
    int len = seq_lens[b];
    if (t0 >= len) return;
    int tid = threadIdx.x;

    for (int idx = tid; idx < 64 * GH; idx += 512) {
        int k = idx >> 8, c = idx & 255;
        Wt[k * WPAD + c] = f2tf32(gate_kernel[k * GH + c]);
    }
    for (int idx = tid; idx < 64 * H_DIM; idx += 512) {
        int k = idx >> 7, c = idx & 127;
        Wt[k * WPAD + 256 + c] = f2tf32(cand_kernel[k * H_DIM + c]);
    }
    if (tid < 256) bs[tid] = gate_bias[tid];
    else if (tid < 384) bs[tid] = cand_bias[tid - 256];
    if (tid < 64) items_s[tid] = item_his[b * T_DIM + t0 + tid];
    __syncthreads();

    for (int e = tid; e < 64 * 64; e += 512) {
        int rr = e >> 6, k = e & 63;
        xs[rr * XPAD + k] = f2tf32(embedding[items_s[rr] * 64 + k]);
    }
    __syncthreads();

    int warp = tid >> 5, lane = tid & 31;
    int wm = warp & 3;
    int wn = warp >> 2;
    int rbase = wm * 16;
    int nbase = wn * 96;

    float c[12][4];
    #pragma unroll
    for (int nt = 0; nt < 12; nt++)
        #pragma unroll
        for (int q = 0; q < 4; q++) c[nt][q] = 0.0f;

    int ar = rbase + (lane >> 2);
    int ac0 = lane & 3;

    #pragma unroll
    for (int k0 = 0; k0 < 8; k0++) {
        int ka = k0 * 8;
        unsigned a0 = xs[ar * XPAD + ka + ac0];
        unsigned a1 = xs[(ar + 8) * XPAD + ka + ac0];
        unsigned a2 = xs[ar * XPAD + ka + ac0 + 4];
        unsigned a3 = xs[(ar + 8) * XPAD + ka + ac0 + 4];
        const unsigned* Wrow0 = Wt + (ka + (lane & 3)) * WPAD + (lane >> 2);
        const unsigned* Wrow1 = Wrow0 + 4 * WPAD;
        #pragma unroll
        for (int nt = 0; nt < 12; nt++) {
            unsigned b0 = Wrow0[nbase + nt * 8];
            unsigned b1 = Wrow1[nbase + nt * 8];
            mma_tf32(c[nt][0], c[nt][1], c[nt][2], c[nt][3], a0, a1, a2, a3, b0, b1);
        }
    }

    __syncthreads();
    float* Xst = (float*)Wt;
    int row0 = rbase + (lane >> 2);
    #pragma unroll
    for (int nt = 0; nt < 12; nt++) {
        int col = nbase + nt * 8 + 2 * (lane & 3);
        Xst[row0 * WPAD + col]           = c[nt][0];
        Xst[row0 * WPAD + col + 1]       = c[nt][1];
        Xst[(row0 + 8) * WPAD + col]     = c[nt][2];
        Xst[(row0 + 8) * WPAD + col + 1] = c[nt][3];
    }
    __syncthreads();

    const float4* bias4 = (const float4*)bs;
    for (int rr = warp; rr < 64; rr += 16) {
        float4* dst = (float4*)(g_Xbuf + (size_t)(b * T_DIM + t0 + rr) * XCOLS);
        const float4* src = (const float4*)(Xst + rr * WPAD);
        #pragma unroll
        for (int cc = lane; cc < 96; cc += 32) {
            float4 v = src[cc], bb = bias4[cc];
            v.x += bb.x; v.y += bb.y; v.z += bb.z; v.w += bb.w;
            dst[cc] = v;
        }
    }
}

// ---------------------------------------------------------------------------
// K2: persistent GRU on fp16 tensor cores — 512 threads, 8 rows/group,
// ONE group per CTA (128 CTAs; no queue). Warp w: gate cols [16w,16w+16),
// cand cols [8w,8w+8). B-fragments in regs; h fp32 + half2 mirror;
// x prefetched one step ahead; tanh.approx activations.
// Fragment rows: lane l handles row r = l>>2 (real, 0..7); rows 8..15 zero.
// ---------------------------------------------------------------------------
__global__ void __launch_bounds__(512, 1) gru_kernel(
    const int* __restrict__ seq_lens,
    const float* __restrict__ gate_kernel,
    const float* __restrict__ cand_kernel,
    float* __restrict__ out)
{
    __shared__ float    h_s[RROWS * HP];       // fp32 master state
    __shared__ unsigned h2_s[RROWS * HP2];     // half2 mirror of h
    __shared__ unsigned rh2_s[RROWS * HP2];    // half2 of r*h
    __shared__ float    u_s[RROWS * H_DIM];
    __shared__ int s_b[RROWS];
    __shared__ int s_len[RROWS];

    int g = blockIdx.x;                        // one group per CTA
    int tid = threadIdx.x;
    int w   = tid >> 5;          // 0..15
    int l   = tid & 31;
    int r   = l >> 2;            // fragment row, 0..7 (all real)
    int c0  = l & 3;

    // ---- fp16 B-fragments in registers (one-time) ----
    unsigned wg0[2][8], wg1[2][8];
    #pragma unroll
    for (int nt = 0; nt < 2; nt++)
        #pragma unroll
        for (int kt = 0; kt < 8; kt++) {
            int k = D_DIM + 16 * kt + 2 * c0;
            int n = 16 * w + 8 * nt + (l >> 2);
            wg0[nt][kt] = pack_h2(gate_kernel[k * GH + n],       gate_kernel[(k + 1) * GH + n]);
            wg1[nt][kt] = pack_h2(gate_kernel[(k + 8) * GH + n], gate_kernel[(k + 9) * GH + n]);
        }
    unsigned wc0[8], wc1[8];
    #pragma unroll
    for (int kt = 0; kt < 8; kt++) {
        int k = D_DIM + 16 * kt + 2 * c0;
        int n = 8 * w + (l >> 2);
        wc0[kt] = pack_h2(cand_kernel[k * H_DIM + n],       cand_kernel[(k + 1) * H_DIM + n]);
        wc1[kt] = pack_h2(cand_kernel[(k + 8) * H_DIM + n], cand_kernel[(k + 9) * H_DIM + n]);
    }

    if (tid < RROWS) {
        int row = g_perm[g * RROWS + tid];
        s_b[tid]   = row;
        s_len[tid] = min(max(seq_lens[row], 0), T_DIM);
    }
    for (int e = tid; e < RROWS * HP; e += 512) h_s[e] = 0.0f;
    for (int e = tid; e < RROWS * HP2; e += 512) h2_s[e] = 0u;
    __syncthreads();

    int L = 0;
    #pragma unroll
    for (int q = 0; q < RROWS; q++) L = max(L, s_len[q]);
    int mylen = s_len[r];
    int xbase = s_b[r] * (T_DIM * XCOLS);
    int xg0c = 16 * w + 2 * c0;            // gate col base for this lane
    int xcc  = 256 + 8 * w + 2 * c0;       // cand col base
    int colc = 8 * w + 2 * c0;             // cand/h update col

    // preload x for t = 0
    float2 vg0 = make_float2(0.f, 0.f), vg1 = vg0, vc = vg0;
    if (L > 0) {
        vg0 = *(const float2*)(g_Xbuf + xbase + xg0c);
        vg1 = *(const float2*)(g_Xbuf + xbase + xg0c + 8);
        vc  = *(const float2*)(g_Xbuf + xbase + xcc);
    }

    for (int t = 0; t < L; t++) {
        // prefetch x for t+1 (hidden behind this step's compute)
        float2 nvg0 = vg0, nvg1 = vg1, nvc = vc;
        if (t + 1 < L) {
            int toff2 = xbase + (t + 1) * XCOLS;
            nvg0 = *(const float2*)(g_Xbuf + toff2 + xg0c);
            nvg1 = *(const float2*)(g_Xbuf + toff2 + xg0c + 8);
            nvc  = *(const float2*)(g_Xbuf + toff2 + xcc);
        }

        // ---- gate MMA: [16x128] h (rows 8-15 zero) x [128x16], fp16 k16 ----
        float cg[2][4];
        cg[0][0]=cg[0][1]=cg[0][2]=cg[0][3]=0.f;
        cg[1][0]=cg[1][1]=cg[1][2]=cg[1][3]=0.f;
        #pragma unroll
        for (int kt = 0; kt < 8; kt++) {
            unsigned a0 = h2_s[r * HP2 + 8 * kt + c0];
            unsigned a2 = h2_s[r * HP2 + 8 * kt + c0 + 4];
            #pragma unroll
            for (int nt = 0; nt < 2; nt++)
                mma_f16(cg[nt][0], cg[nt][1], cg[nt][2], cg[nt][3],
                        a0, 0u, a2, 0u, wg0[nt][kt], wg1[nt][kt]);
        }
        {
            float s0a = sigmoid_fast(cg[0][0] + vg0.x);
            float s1a = sigmoid_fast(cg[0][1] + vg0.y);
            float s0b = sigmoid_fast(cg[1][0] + vg1.x);
            float s1b = sigmoid_fast(cg[1][1] + vg1.y);
            int colA = 16 * w + 2 * c0;
            int colB = colA + 8;
            if (w < 8) {        // r-gate (cols 0..127)
                rh2_s[r * HP2 + (colA >> 1)] =
                    pack_h2(s0a * h_s[r * HP + colA], s1a * h_s[r * HP + colA + 1]);
                rh2_s[r * HP2 + (colB >> 1)] =
                    pack_h2(s0b * h_s[r * HP + colB], s1b * h_s[r * HP + colB + 1]);
            } else {            // u-gate (cols 128..255)
                *(float2*)(u_s + r * H_DIM + (colA - 128)) = make_float2(s0a, s1a);
                *(float2*)(u_s + r * H_DIM + (colB - 128)) = make_float2(s0b, s1b);
            }
        }
        __syncthreads();

        // ---- cand MMA: [16x128] r*h x [128x8], fp16 k16 ----
        float cd[4];
        cd[0]=cd[1]=cd[2]=cd[3]=0.f;
        #pragma unroll
        for (int kt = 0; kt < 8; kt++) {
            unsigned a0 = rh2_s[r * HP2 + 8 * kt + c0];
            unsigned a2 = rh2_s[r * HP2 + 8 * kt + c0 + 4];
            mma_f16(cd[0], cd[1], cd[2], cd[3],
                    a0, 0u, a2, 0u, wc0[kt], wc1[kt]);
        }
        {
            float cc0 = tanh_fast(cd[0] + vc.x);
            float cc1 = tanh_fast(cd[1] + vc.y);
            float u0 = u_s[r * H_DIM + colc];
            float u1 = u_s[r * H_DIM + colc + 1];
            float h0 = h_s[r * HP + colc];
            float h1 = h_s[r * HP + colc + 1];
            if (t < mylen) {
                float n0 = fmaf(u0, h0 - cc0, cc0);   // u*h+(1-u)*c
                float n1 = fmaf(u1, h1 - cc1, cc1);
                h_s[r * HP + colc]     = n0;
                h_s[r * HP + colc + 1] = n1;
                h2_s[r * HP2 + (colc >> 1)] = pack_h2(n0, n1);
            }
        }
        __syncthreads();

        vg0 = nvg0; vg1 = nvg1; vc = nvc;
    }

    *(float2*)(out + s_b[r] * H_DIM + colc) =
        make_float2(h_s[r * HP + colc], h_s[r * HP + colc + 1]);
}

// ---------------------------------------------------------------------------
extern "C" void kernel_launch(void* const* d_in, const int* in_sizes, int n_in,
                              void* d_out, int out_size) {
    (void)in_sizes; (void)n_in; (void)out_size;
    const int*   item_his    = (const int*)  d_in[0];
    const int*   seq_lens    = (const int*)  d_in[1];
    const float* embedding   = (const float*)d_in[2];
    const float* gate_kernel = (const float*)d_in[3];
    const float* gate_bias   = (const float*)d_in[4];
    const float* cand_kernel = (const float*)d_in[5];
    const float* cand_bias   = (const float*)d_in[6];
    float*       out         = (float*)d_out;

    const int smem_proj = (64 * XPAD + 64 * WPAD + 384) * 4;   // ~119 KB
    cudaFuncSetAttribute(proj_kernel, cudaFuncAttributeMaxDynamicSharedMemorySize, smem_proj);

    sort_kernel<<<1, 256>>>(seq_lens);
    proj_kernel<<<dim3(T_DIM / 64, B_DIM), 512, smem_proj>>>(
        item_his, seq_lens, embedding, gate_kernel, gate_bias, cand_kernel, cand_bias);
    gru_kernel<<<NGROUPS, 512>>>(seq_lens, gate_kernel, cand_kernel, out);
}

// round 15
// speedup vs baseline: 1.0572x; 1.0572x over previous
#include <cuda_runtime.h>
#include <cuda_fp16.h>

#define B_DIM 1024
#define T_DIM 256
#define D_DIM 64
#define H_DIM 128
#define GH 256          // 2H
#define XCOLS 384       // 256 gate cols + 128 cand cols
#define RROWS 4
#define NGROUPS (B_DIM / RROWS)   // 256
#define XPAD 68         // proj x smem stride
#define WPAD 392        // proj W smem stride
#define HP 132          // gru fp32 h row stride (floats)
#define HP2 68          // gru half2 row stride (uint32 units)

// Scratch (device globals: no allocation allowed).
static __device__ float g_Xbuf[(size_t)B_DIM * T_DIM * XCOLS]; // ~402 MB
static __device__ int   g_perm[B_DIM];
static __device__ int   g_counter;

__device__ __forceinline__ float tanh_fast(float z) {
    float r;
    asm("tanh.approx.f32 %0, %1;" : "=f"(r) : "f"(z));
    return r;
}
__device__ __forceinline__ float sigmoid_fast(float z) {
    return fmaf(0.5f, tanh_fast(0.5f * z), 0.5f);
}
__device__ __forceinline__ unsigned f2tf32(float f) {
    unsigned u;
    asm("cvt.rna.tf32.f32 %0, %1;" : "=r"(u) : "f"(f));
    return u;
}
__device__ __forceinline__ unsigned pack_h2(float lo, float hi) {
    __half2 h = __floats2half2_rn(lo, hi);
    return *(unsigned*)&h;
}
__device__ __forceinline__ void mma_tf32(float& c0, float& c1, float& c2, float& c3,
                                         unsigned a0, unsigned a1, unsigned a2, unsigned a3,
                                         unsigned b0, unsigned b1) {
    asm("mma.sync.aligned.m16n8k8.row.col.f32.tf32.tf32.f32 "
        "{%0,%1,%2,%3}, {%4,%5,%6,%7}, {%8,%9}, {%0,%1,%2,%3};"
        : "+f"(c0), "+f"(c1), "+f"(c2), "+f"(c3)
        : "r"(a0), "r"(a1), "r"(a2), "r"(a3), "r"(b0), "r"(b1));
}
__device__ __forceinline__ void mma_f16(float& c0, float& c1, float& c2, float& c3,
                                        unsigned a0, unsigned a1, unsigned a2, unsigned a3,
                                        unsigned b0, unsigned b1) {
    asm("mma.sync.aligned.m16n8k16.row.col.f32.f16.f16.f32 "
        "{%0,%1,%2,%3}, {%4,%5,%6,%7}, {%8,%9}, {%0,%1,%2,%3};"
        : "+f"(c0), "+f"(c1), "+f"(c2), "+f"(c3)
        : "r"(a0), "r"(a1), "r"(a2), "r"(a3), "r"(b0), "r"(b1));
}

// ---------------------------------------------------------------------------
// K0: counting sort rows by seq_len (descending, LPT) + reset work counter.
// ---------------------------------------------------------------------------
__global__ void sort_kernel(const int* __restrict__ seq_lens) {
    __shared__ int hist[256];
    __shared__ int offs[256];
    int tid = threadIdx.x;
    hist[tid] = 0;
    __syncthreads();
    for (int r = tid; r < B_DIM; r += 256) {
        int L = seq_lens[r];
        L = min(max(L, 0), 255);
        atomicAdd(&hist[L], 1);
    }
    __syncthreads();
    if (tid == 0) {
        int run = 0;
        for (int k = 255; k >= 0; k--) { offs[k] = run; run += hist[k]; }
        g_counter = 0;
    }
    __syncthreads();
    for (int r = tid; r < B_DIM; r += 256) {
        int L = seq_lens[r];
        L = min(max(L, 0), 255);
        int pos = atomicAdd(&offs[L], 1);
        g_perm[pos] = r;
    }
}

// ---------------------------------------------------------------------------
// K1: projection via tf32 tensor cores + smem-staged coalesced epilogue.
// (unchanged — validated at R10)
// ---------------------------------------------------------------------------
__global__ void __launch_bounds__(512) proj_kernel(
    const int* __restrict__ item_his,
    const int* __restrict__ seq_lens,
    const float* __restrict__ embedding,
    const float* __restrict__ gate_kernel,
    const float* __restrict__ gate_bias,
    const float* __restrict__ cand_kernel,
    const float* __restrict__ cand_bias)
{
    extern __shared__ unsigned smu[];
    unsigned* xs = smu;                      // [64][XPAD]
    unsigned* Wt = xs + 64 * XPAD;           // [64][WPAD] (reused as stage)
    float*    bs = (float*)(Wt + 64 * WPAD); // [384]
    __shared__ int items_s[64];

    int b  = blockIdx.y;
    int t0 = blockIdx.x * 64;
    int len = seq_lens[b];
    if (t0 >= len) return;
    int tid = threadIdx.x;

    for (int idx = tid; idx < 64 * GH; idx += 512) {
        int k = idx >> 8, c = idx & 255;
        Wt[k * WPAD + c] = f2tf32(gate_kernel[k * GH + c]);
    }
    for (int idx = tid; idx < 64 * H_DIM; idx += 512) {
        int k = idx >> 7, c = idx & 127;
        Wt[k * WPAD + 256 + c] = f2tf32(cand_kernel[k * H_DIM + c]);
    }
    if (tid < 256) bs[tid] = gate_bias[tid];
    else if (tid < 384) bs[tid] = cand_bias[tid - 256];
    if (tid < 64) items_s[tid] = item_his[b * T_DIM + t0 + tid];
    __syncthreads();

    for (int e = tid; e < 64 * 64; e += 512) {
        int rr = e >> 6, k = e & 63;
        xs[rr * XPAD + k] = f2tf32(embedding[items_s[rr] * 64 + k]);
    }
    __syncthreads();

    int warp = tid >> 5, lane = tid & 31;
    int wm = warp & 3;
    int wn = warp >> 2;
    int rbase = wm * 16;
    int nbase = wn * 96;

    float c[12][4];
    #pragma unroll
    for (int nt = 0; nt < 12; nt++)
        #pragma unroll
        for (int q = 0; q < 4; q++) c[nt][q] = 0.0f;

    int ar = rbase + (lane >> 2);
    int ac0 = lane & 3;

    #pragma unroll
    for (int k0 = 0; k0 < 8; k0++) {
        int ka = k0 * 8;
        unsigned a0 = xs[ar * XPAD + ka + ac0];
        unsigned a1 = xs[(ar + 8) * XPAD + ka + ac0];
        unsigned a2 = xs[ar * XPAD + ka + ac0 + 4];
        unsigned a3 = xs[(ar + 8) * XPAD + ka + ac0 + 4];
        const unsigned* Wrow0 = Wt + (ka + (lane & 3)) * WPAD + (lane >> 2);
        const unsigned* Wrow1 = Wrow0 + 4 * WPAD;
        #pragma unroll
        for (int nt = 0; nt < 12; nt++) {
            unsigned b0 = Wrow0[nbase + nt * 8];
            unsigned b1 = Wrow1[nbase + nt * 8];
            mma_tf32(c[nt][0], c[nt][1], c[nt][2], c[nt][3], a0, a1, a2, a3, b0, b1);
        }
    }

    __syncthreads();
    float* Xst = (float*)Wt;
    int row0 = rbase + (lane >> 2);
    #pragma unroll
    for (int nt = 0; nt < 12; nt++) {
        int col = nbase + nt * 8 + 2 * (lane & 3);
        Xst[row0 * WPAD + col]           = c[nt][0];
        Xst[row0 * WPAD + col + 1]       = c[nt][1];
        Xst[(row0 + 8) * WPAD + col]     = c[nt][2];
        Xst[(row0 + 8) * WPAD + col + 1] = c[nt][3];
    }
    __syncthreads();

    const float4* bias4 = (const float4*)bs;
    for (int rr = warp; rr < 64; rr += 16) {
        float4* dst = (float4*)(g_Xbuf + (size_t)(b * T_DIM + t0 + rr) * XCOLS);
        const float4* src = (const float4*)(Xst + rr * WPAD);
        #pragma unroll
        for (int cc = lane; cc < 96; cc += 32) {
            float4 v = src[cc], bb = bias4[cc];
            v.x += bb.x; v.y += bb.y; v.z += bb.z; v.w += bb.w;
            dst[cc] = v;
        }
    }
}

// ---------------------------------------------------------------------------
// K2: persistent GRU on fp16 tensor cores — R13 structure (best @498) with
// tanh.approx activations. 512 threads (16 warps, 4/SMSP), RROWS=4, work
// queue over 256 groups. Warp w: gate cols [16w,16w+16), cand cols [8w,8w+8).
// B-fragments in regs; h fp32 + half2 mirror; x prefetched one step ahead.
// ---------------------------------------------------------------------------
__global__ void __launch_bounds__(512, 1) gru_kernel(
    const int* __restrict__ seq_lens,
    const float* __restrict__ gate_kernel,
    const float* __restrict__ cand_kernel,
    float* __restrict__ out)
{
    __shared__ float    h_s[RROWS * HP];       // fp32 master state
    __shared__ unsigned h2_s[RROWS * HP2];     // half2 mirror of h
    __shared__ unsigned rh2_s[RROWS * HP2];    // half2 of r*h
    __shared__ float    u_s[RROWS * H_DIM];
    __shared__ int s_g;
    __shared__ int s_b[RROWS];
    __shared__ int s_len[RROWS];

    int tid = threadIdx.x;
    int w   = tid >> 5;          // 0..15
    int l   = tid & 31;
    int r   = l >> 2;            // fragment row (real if < 4)
    int c0  = l & 3;
    bool act = (r < RROWS);

    // ---- fp16 B-fragments in registers (one-time) ----
    unsigned wg0[2][8], wg1[2][8];
    #pragma unroll
    for (int nt = 0; nt < 2; nt++)
        #pragma unroll
        for (int kt = 0; kt < 8; kt++) {
            int k = D_DIM + 16 * kt + 2 * c0;
            int n = 16 * w + 8 * nt + (l >> 2);
            wg0[nt][kt] = pack_h2(gate_kernel[k * GH + n],       gate_kernel[(k + 1) * GH + n]);
            wg1[nt][kt] = pack_h2(gate_kernel[(k + 8) * GH + n], gate_kernel[(k + 9) * GH + n]);
        }
    unsigned wc0[8], wc1[8];
    #pragma unroll
    for (int kt = 0; kt < 8; kt++) {
        int k = D_DIM + 16 * kt + 2 * c0;
        int n = 8 * w + (l >> 2);
        wc0[kt] = pack_h2(cand_kernel[k * H_DIM + n],       cand_kernel[(k + 1) * H_DIM + n]);
        wc1[kt] = pack_h2(cand_kernel[(k + 8) * H_DIM + n], cand_kernel[(k + 9) * H_DIM + n]);
    }

    while (true) {
        if (tid == 0) s_g = atomicAdd(&g_counter, 1);
        __syncthreads();
        int g = s_g;
        if (g >= NGROUPS) break;

        if (tid < RROWS) {
            int row = g_perm[g * RROWS + tid];
            s_b[tid]   = row;
            s_len[tid] = min(max(seq_lens[row], 0), T_DIM);
        }
        for (int e = tid; e < RROWS * HP; e += 512) h_s[e] = 0.0f;
        for (int e = tid; e < RROWS * HP2; e += 512) h2_s[e] = 0u;
        __syncthreads();

        int L = max(max(s_len[0], s_len[1]), max(s_len[2], s_len[3]));
        int mylen = act ? s_len[r] : 0;
        int xbase = act ? s_b[r] * (T_DIM * XCOLS) : 0;
        int xg0c = 16 * w + 2 * c0;            // gate col base for this lane
        int xcc  = 256 + 8 * w + 2 * c0;       // cand col base
        int colc = 8 * w + 2 * c0;             // cand/h update col

        // preload x for t = 0
        float2 vg0 = make_float2(0.f, 0.f), vg1 = vg0, vc = vg0;
        if (act && L > 0) {
            vg0 = *(const float2*)(g_Xbuf + xbase + xg0c);
            vg1 = *(const float2*)(g_Xbuf + xbase + xg0c + 8);
            vc  = *(const float2*)(g_Xbuf + xbase + xcc);
        }

        for (int t = 0; t < L; t++) {
            // prefetch x for t+1 (hidden behind this step's compute)
            float2 nvg0 = vg0, nvg1 = vg1, nvc = vc;
            if (act && t + 1 < L) {
                int toff2 = xbase + (t + 1) * XCOLS;
                nvg0 = *(const float2*)(g_Xbuf + toff2 + xg0c);
                nvg1 = *(const float2*)(g_Xbuf + toff2 + xg0c + 8);
                nvc  = *(const float2*)(g_Xbuf + toff2 + xcc);
            }

            // ---- gate MMA: [16x128] h x [128x16], fp16 k16 ----
            float cg[2][4];
            cg[0][0]=cg[0][1]=cg[0][2]=cg[0][3]=0.f;
            cg[1][0]=cg[1][1]=cg[1][2]=cg[1][3]=0.f;
            #pragma unroll
            for (int kt = 0; kt < 8; kt++) {
                unsigned a0 = 0, a2 = 0;
                if (act) {
                    a0 = h2_s[r * HP2 + 8 * kt + c0];
                    a2 = h2_s[r * HP2 + 8 * kt + c0 + 4];
                }
                #pragma unroll
                for (int nt = 0; nt < 2; nt++)
                    mma_f16(cg[nt][0], cg[nt][1], cg[nt][2], cg[nt][3],
                            a0, 0u, a2, 0u, wg0[nt][kt], wg1[nt][kt]);
            }
            if (act) {
                float s0a = sigmoid_fast(cg[0][0] + vg0.x);
                float s1a = sigmoid_fast(cg[0][1] + vg0.y);
                float s0b = sigmoid_fast(cg[1][0] + vg1.x);
                float s1b = sigmoid_fast(cg[1][1] + vg1.y);
                int colA = 16 * w + 2 * c0;
                int colB = colA + 8;
                if (w < 8) {        // r-gate (cols 0..127)
                    rh2_s[r * HP2 + (colA >> 1)] =
                        pack_h2(s0a * h_s[r * HP + colA], s1a * h_s[r * HP + colA + 1]);
                    rh2_s[r * HP2 + (colB >> 1)] =
                        pack_h2(s0b * h_s[r * HP + colB], s1b * h_s[r * HP + colB + 1]);
                } else {            // u-gate (cols 128..255)
                    *(float2*)(u_s + r * H_DIM + (colA - 128)) = make_float2(s0a, s1a);
                    *(float2*)(u_s + r * H_DIM + (colB - 128)) = make_float2(s0b, s1b);
                }
            }
            __syncthreads();

            // ---- cand MMA: [16x128] r*h x [128x8], fp16 k16 ----
            float cd[4];
            cd[0]=cd[1]=cd[2]=cd[3]=0.f;
            #pragma unroll
            for (int kt = 0; kt < 8; kt++) {
                unsigned a0 = 0, a2 = 0;
                if (act) {
                    a0 = rh2_s[r * HP2 + 8 * kt + c0];
                    a2 = rh2_s[r * HP2 + 8 * kt + c0 + 4];
                }
                mma_f16(cd[0], cd[1], cd[2], cd[3],
                        a0, 0u, a2, 0u, wc0[kt], wc1[kt]);
            }
            if (act) {
                float cc0 = tanh_fast(cd[0] + vc.x);
                float cc1 = tanh_fast(cd[1] + vc.y);
                float u0 = u_s[r * H_DIM + colc];
                float u1 = u_s[r * H_DIM + colc + 1];
                float h0 = h_s[r * HP + colc];
                float h1 = h_s[r * HP + colc + 1];
                if (t < mylen) {
                    float n0 = fmaf(u0, h0 - cc0, cc0);   // u*h+(1-u)*c
                    float n1 = fmaf(u1, h1 - cc1, cc1);
                    h_s[r * HP + colc]     = n0;
                    h_s[r * HP + colc + 1] = n1;
                    h2_s[r * HP2 + (colc >> 1)] = pack_h2(n0, n1);
                }
            }
            __syncthreads();

            vg0 = nvg0; vg1 = nvg1; vc = nvc;
        }

        if (act) {
            *(float2*)(out + s_b[r] * H_DIM + colc) =
                make_float2(h_s[r * HP + colc], h_s[r * HP + colc + 1]);
        }
        __syncthreads();
    }
}

// ---------------------------------------------------------------------------
extern "C" void kernel_launch(void* const* d_in, const int* in_sizes, int n_in,
                              void* d_out, int out_size) {
    (void)in_sizes; (void)n_in; (void)out_size;
    const int*   item_his    = (const int*)  d_in[0];
    const int*   seq_lens    = (const int*)  d_in[1];
    const float* embedding   = (const float*)d_in[2];
    const float* gate_kernel = (const float*)d_in[3];
    const float* gate_bias   = (const float*)d_in[4];
    const float* cand_kernel = (const float*)d_in[5];
    const float* cand_bias   = (const float*)d_in[6];
    float*       out         = (float*)d_out;

    const int smem_proj = (64 * XPAD + 64 * WPAD + 384) * 4;   // ~119 KB
    cudaFuncSetAttribute(proj_kernel, cudaFuncAttributeMaxDynamicSharedMemorySize, smem_proj);

    sort_kernel<<<1, 256>>>(seq_lens);
    proj_kernel<<<dim3(T_DIM / 64, B_DIM), 512, smem_proj>>>(
        item_his, seq_lens, embedding, gate_kernel, gate_bias, cand_kernel, cand_bias);
    gru_kernel<<<148, 512>>>(seq_lens, gate_kernel, cand_kernel, out);
}